// round 1
// baseline (speedup 1.0000x reference)
#include <cuda_runtime.h>
#include <cstdint>

#define VOCAB 50257
#define EMBED 256
#define HID   128
#define G4    512   // 4*HID
#define BATCH 128
#define SEQ   1024

// Gate-projection table: table[v][g] = sum_e emb[v][e]*W_ih[g][e] + b_ih[g]+b_hh[g]
__device__ float g_table[(size_t)VOCAB * G4];

// ---------------- packed fp32x2 helpers ----------------
__device__ __forceinline__ unsigned long long pack2(float lo, float hi) {
    unsigned long long r;
    asm("mov.b64 %0, {%1, %2};" : "=l"(r) : "f"(lo), "f"(hi));
    return r;
}
__device__ __forceinline__ unsigned long long splat2(float x) {
    unsigned long long r;
    asm("mov.b64 %0, {%1, %1};" : "=l"(r) : "f"(x));
    return r;
}
__device__ __forceinline__ void unpack2(unsigned long long v, float& lo, float& hi) {
    asm("mov.b64 {%0, %1}, %2;" : "=f"(lo), "=f"(hi) : "l"(v));
}
__device__ __forceinline__ void ffma2(unsigned long long& d, unsigned long long a, unsigned long long b) {
    asm("fma.rn.f32x2 %0, %1, %2, %0;" : "+l"(d) : "l"(a), "l"(b));
}

__device__ __forceinline__ float sigmoidf_fast(float z) {
    float e = __expf(-z);
    return __fdividef(1.0f, 1.0f + e);
}
__device__ __forceinline__ float tanhf_fast(float z) {
    // tanh(z) = 1 - 2/(exp(2z)+1); handles +/-inf saturation correctly
    float e = __expf(2.0f * z);
    return 1.0f - __fdividef(2.0f, e + 1.0f);
}

// =====================================================================
// Kernel 1: table[v][g] = emb[v] . W_ih[g] + bias[g]
// Tile: 64 vocab x 128 gates per CTA, 256 threads, 4x8 microtile, FFMA2.
// =====================================================================
#define BV 64
#define BG 128
#define KC 16

__global__ void __launch_bounds__(256) table_kernel(
    const float* __restrict__ emb,
    const float* __restrict__ W_ih,
    const float* __restrict__ b_ih,
    const float* __restrict__ b_hh)
{
    __shared__ float As[KC][BV + 4];   // transposed: As[k][v], stride 68
    __shared__ float Bs[KC][BG + 4];   // transposed: Bs[k][g], stride 132

    const int v0 = blockIdx.x * BV;
    const int g0 = blockIdx.y * BG;
    const int tid = threadIdx.x;
    const int ty = tid >> 4;     // 0..15  (vocab quad)
    const int tx = tid & 15;     // 0..15  (gate octet)

    const int arow = tid >> 2;   // 0..63
    const int akq  = tid & 3;    // 0..3

    unsigned long long acc[4][4];
#pragma unroll
    for (int i = 0; i < 4; i++)
#pragma unroll
        for (int p = 0; p < 4; p++) acc[i][p] = 0ull;

    const int vload = min(v0 + arow, VOCAB - 1);

    for (int k0 = 0; k0 < EMBED; k0 += KC) {
        // load A tile (emb rows), transpose into SMEM
        float4 a = *(const float4*)(emb + (size_t)vload * EMBED + k0 + akq * 4);
        As[akq * 4 + 0][arow] = a.x;
        As[akq * 4 + 1][arow] = a.y;
        As[akq * 4 + 2][arow] = a.z;
        As[akq * 4 + 3][arow] = a.w;
        // load B tile (W_ih rows), two rows per thread
        float4 w0 = *(const float4*)(W_ih + (size_t)(g0 + arow)      * EMBED + k0 + akq * 4);
        float4 w1 = *(const float4*)(W_ih + (size_t)(g0 + 64 + arow) * EMBED + k0 + akq * 4);
        Bs[akq * 4 + 0][arow] = w0.x;  Bs[akq * 4 + 0][64 + arow] = w1.x;
        Bs[akq * 4 + 1][arow] = w0.y;  Bs[akq * 4 + 1][64 + arow] = w1.y;
        Bs[akq * 4 + 2][arow] = w0.z;  Bs[akq * 4 + 2][64 + arow] = w1.z;
        Bs[akq * 4 + 3][arow] = w0.w;  Bs[akq * 4 + 3][64 + arow] = w1.w;
        __syncthreads();

#pragma unroll
        for (int k = 0; k < KC; k++) {
            float4 av = *(const float4*)&As[k][ty * 4];
            float4 bl = *(const float4*)&Bs[k][tx * 8];
            float4 bh = *(const float4*)&Bs[k][tx * 8 + 4];
            unsigned long long b2[4];
            b2[0] = pack2(bl.x, bl.y);
            b2[1] = pack2(bl.z, bl.w);
            b2[2] = pack2(bh.x, bh.y);
            b2[3] = pack2(bh.z, bh.w);
            unsigned long long a0 = splat2(av.x);
            unsigned long long a1 = splat2(av.y);
            unsigned long long a2 = splat2(av.z);
            unsigned long long a3 = splat2(av.w);
#pragma unroll
            for (int p = 0; p < 4; p++) {
                ffma2(acc[0][p], a0, b2[p]);
                ffma2(acc[1][p], a1, b2[p]);
                ffma2(acc[2][p], a2, b2[p]);
                ffma2(acc[3][p], a3, b2[p]);
            }
        }
        __syncthreads();
    }

    // epilogue: add bias, store
    const int gbase = g0 + tx * 8;
    float bz[8];
#pragma unroll
    for (int c = 0; c < 8; c++) bz[c] = b_ih[gbase + c] + b_hh[gbase + c];

#pragma unroll
    for (int i = 0; i < 4; i++) {
        int v = v0 + ty * 4 + i;
        if (v < VOCAB) {
            float r[8];
#pragma unroll
            for (int p = 0; p < 4; p++) {
                float lo, hi;
                unpack2(acc[i][p], lo, hi);
                r[2 * p]     = lo + bz[2 * p];
                r[2 * p + 1] = hi + bz[2 * p + 1];
            }
            float4 s0 = make_float4(r[0], r[1], r[2], r[3]);
            float4 s1 = make_float4(r[4], r[5], r[6], r[7]);
            float* dst = &g_table[(size_t)v * G4 + gbase];
            *(float4*)(dst)     = s0;
            *(float4*)(dst + 4) = s1;
        }
    }
}

// =====================================================================
// Kernel 2: per-batch LSTM recurrence. 128 CTAs x 512 threads.
// Thread g owns gate g; W_hh row g split: k[0,96) in regs (48 f32x2),
// k[96,128) in SMEM (16 ull per gate). h broadcast via SMEM.
// =====================================================================
#define KREG_PAIRS 48   // 96 k-values in registers
#define KSM_PAIRS  16   // 32 k-values in SMEM

struct __align__(16) LstmSmem {
    unsigned long long wsm[KSM_PAIRS][G4]; // 64 KB
    float hbuf[HID];                       // current hidden state
    float gact[G4];                        // activated gates / head scratch
    int   toks[SEQ];                       // token ids for this batch row
};

__global__ void __launch_bounds__(512, 1) lstm_kernel(
    const void* __restrict__ xraw,
    const float* __restrict__ W_hh,
    const float* __restrict__ W_fc,
    const float* __restrict__ b_fc,
    float* __restrict__ out)
{
    extern __shared__ char smem_raw[];
    LstmSmem* S = (LstmSmem*)smem_raw;

    const int b = blockIdx.x;
    const int g = threadIdx.x;

    // --- detect whether x is stored as int64 or int32 (JAX x64 may demote) ---
    bool is64;
    {
        const int* xi = (const int*)xraw;
        int val = xi[2 * (g & 31) + 1];           // odd 32-bit words of first 64 words
        unsigned m = __ballot_sync(0xffffffffu, val != 0);
        is64 = (m == 0u);                          // int64 hi-words are all zero
    }

    // --- preload this batch row's tokens into SMEM ---
    if (is64) {
        const long long* x64 = (const long long*)xraw;
        for (int i = g; i < SEQ; i += 512) S->toks[i] = (int)x64[(size_t)b * SEQ + i];
    } else {
        const int* x32 = (const int*)xraw;
        for (int i = g; i < SEQ; i += 512) S->toks[i] = x32[(size_t)b * SEQ + i];
    }

    // --- load W_hh row g: 48 pairs to registers, 16 pairs to SMEM ---
    const float2* wrow = (const float2*)(W_hh + (size_t)g * HID);
    unsigned long long wreg[KREG_PAIRS];
#pragma unroll
    for (int j = 0; j < KREG_PAIRS; j++) {
        float2 w = wrow[j];
        wreg[j] = pack2(w.x, w.y);
    }
#pragma unroll
    for (int j = 0; j < KSM_PAIRS; j++) {
        float2 w = wrow[KREG_PAIRS + j];
        S->wsm[j][g] = pack2(w.x, w.y);
    }

    if (g < HID) S->hbuf[g] = 0.0f;
    float c = 0.0f;
    __syncthreads();

    const float* tab = (const float*)g_table;
    float xg_next = tab[(size_t)S->toks[0] * G4 + g];

    for (int t = 0; t < SEQ; t++) {
        float xv = xg_next;
        if (t + 1 < SEQ) {
            xg_next = tab[(size_t)S->toks[t + 1] * G4 + g];   // prefetch next step
        }

        // gate preactivation: xv + W_hh[g] . h
        unsigned long long acc = pack2(xv, 0.0f);
        const ulonglong2* h4 = (const ulonglong2*)S->hbuf;
#pragma unroll
        for (int jj = 0; jj < 24; jj++) {           // k pairs 0..47 (registers)
            ulonglong2 hv = h4[jj];
            ffma2(acc, wreg[2 * jj],     hv.x);
            ffma2(acc, wreg[2 * jj + 1], hv.y);
        }
#pragma unroll
        for (int jj = 24; jj < 32; jj++) {          // k pairs 48..63 (SMEM)
            ulonglong2 hv = h4[jj];
            unsigned long long w0 = S->wsm[2 * (jj - 24)][g];
            unsigned long long w1 = S->wsm[2 * (jj - 24) + 1][g];
            ffma2(acc, w0, hv.x);
            ffma2(acc, w1, hv.y);
        }
        float lo, hi;
        unpack2(acc, lo, hi);
        float z = lo + hi;

        float a;
        if (g < 256)       a = sigmoidf_fast(z);   // i, f gates
        else if (g < 384)  a = tanhf_fast(z);      // g gate
        else               a = sigmoidf_fast(z);   // o gate
        S->gact[g] = a;
        __syncthreads();

        if (g < HID) {
            float gi = S->gact[g];
            float gf = S->gact[HID + g];
            float gg = S->gact[2 * HID + g];
            float go = S->gact[3 * HID + g];
            c = gf * c + gi * gg;
            S->hbuf[g] = go * tanhf_fast(c);
        }
        __syncthreads();
    }

    // --- final linear head: out[b][cls] = h . W_fc[cls] + b_fc[cls] ---
    if (g < 256) {
        int cls = g >> 7;
        int j   = g & 127;
        S->gact[g] = S->hbuf[j] * W_fc[cls * HID + j];
    }
    __syncthreads();
    if (g < 2) {
        float s = b_fc[g];
#pragma unroll 8
        for (int j = 0; j < HID; j++) s += S->gact[g * HID + j];
        out[b * 2 + g] = s;
    }
}

// =====================================================================
extern "C" void kernel_launch(void* const* d_in, const int* in_sizes, int n_in,
                              void* d_out, int out_size)
{
    const void*  x     = d_in[0];
    const float* emb   = (const float*)d_in[1];
    const float* W_ih  = (const float*)d_in[2];
    const float* W_hh  = (const float*)d_in[3];
    const float* b_ih  = (const float*)d_in[4];
    const float* b_hh  = (const float*)d_in[5];
    const float* W_fc  = (const float*)d_in[6];
    const float* b_fc  = (const float*)d_in[7];
    float* out = (float*)d_out;

    dim3 tgrid((VOCAB + BV - 1) / BV, G4 / BG);   // 786 x 4
    table_kernel<<<tgrid, 256>>>(emb, W_ih, b_ih, b_hh);

    const int smem_bytes = (int)sizeof(LstmSmem);
    cudaFuncSetAttribute(lstm_kernel, cudaFuncAttributeMaxDynamicSharedMemorySize, smem_bytes);
    lstm_kernel<<<BATCH, 512, smem_bytes>>>(x, W_hh, W_fc, b_fc, out);
}